// round 6
// baseline (speedup 1.0000x reference)
#include <cuda_runtime.h>
#include <cuda_bf16.h>
#include <cstdint>

typedef unsigned long long ull;

// ---------------- problem constants ----------------
#define Bc      2
#define Sc      2048
#define HIDc    2048
#define NHc     16
#define NKVc    8
#define HDc     128
#define GATEc   16
#define KVDIMc  (NKVc * HDc)          // 1024
#define QKVOUTc (HIDc + GATEc + 2 * KVDIMc)  // 4112
#define Mrows   (Bc * Sc)             // 4096
#define K_OFF   (HIDc + GATEc)        // 2064
#define V_OFF   (HIDc + GATEc + KVDIMc) // 3088

// ---------------- scratch (no allocations allowed) ----------------
__device__ float g_qkv[(size_t)Mrows * QKVOUTc];   // ~67 MB
__device__ float g_attn[(size_t)Mrows * HIDc];     // ~34 MB

// ---------------- f32x2 packed-FMA helpers ----------------
__device__ __forceinline__ ull pack2(float lo, float hi) {
    ull r;
    asm("mov.b64 %0, {%1, %2};" : "=l"(r) : "f"(lo), "f"(hi));
    return r;
}
__device__ __forceinline__ float2 unpack2(ull v) {
    float2 f;
    asm("mov.b64 {%0, %1}, %2;" : "=f"(f.x), "=f"(f.y) : "l"(v));
    return f;
}
__device__ __forceinline__ void fma2(ull& d, ull a, ull b) {
    asm("fma.rn.f32x2 %0, %1, %2, %0;" : "+l"(d) : "l"(a), "l"(b));
}
__device__ __forceinline__ void mul2(ull& d, ull a) {
    asm("mul.rn.f32x2 %0, %0, %1;" : "+l"(d) : "l"(a));
}

// =====================================================================
// Generic C[M,N] = A[M,K] @ B[N,K]^T  (both row-major, K contiguous)
// 128x128 tile, BK=16, 256 threads, 8 rows x 4 col-pairs per thread (f32x2)
// =====================================================================
__global__ __launch_bounds__(256, 2) void sgemm_nt(
    const float* __restrict__ A, const float* __restrict__ B,
    float* __restrict__ C, int M, int N, int K)
{
    __shared__ float As[16][132];
    __shared__ float Bs[16][132];

    const int tid = threadIdx.x;
    const int m0 = blockIdx.y * 128;
    const int n0 = blockIdx.x * 128;
    const int tx = tid & 15;        // col group
    const int ty = tid >> 4;        // row group

    ull acc[8][4];
#pragma unroll
    for (int i = 0; i < 8; i++)
#pragma unroll
        for (int u = 0; u < 4; u++) acc[i][u] = 0ull;

    const int lr = tid >> 2;        // 0..63 (tile row within load pass)
    const int lk = tid & 3;         // 0..3  (float4 index within 16 k's)

    for (int k0 = 0; k0 < K; k0 += 16) {
#pragma unroll
        for (int t = 0; t < 2; t++) {
            const int row = lr + t * 64;
            float4 a4 = *(const float4*)(A + (size_t)(m0 + row) * K + k0 + lk * 4);
            As[lk * 4 + 0][row] = a4.x;
            As[lk * 4 + 1][row] = a4.y;
            As[lk * 4 + 2][row] = a4.z;
            As[lk * 4 + 3][row] = a4.w;
            const int n = n0 + row;
            float4 b4 = make_float4(0.f, 0.f, 0.f, 0.f);
            if (n < N) b4 = *(const float4*)(B + (size_t)n * K + k0 + lk * 4);
            Bs[lk * 4 + 0][row] = b4.x;
            Bs[lk * 4 + 1][row] = b4.y;
            Bs[lk * 4 + 2][row] = b4.z;
            Bs[lk * 4 + 3][row] = b4.w;
        }
        __syncthreads();

#pragma unroll
        for (int kk = 0; kk < 16; kk++) {
            float4 a0 = *(const float4*)&As[kk][ty * 8];
            float4 a1 = *(const float4*)&As[kk][ty * 8 + 4];
            float av[8];
            av[0] = a0.x; av[1] = a0.y; av[2] = a0.z; av[3] = a0.w;
            av[4] = a1.x; av[5] = a1.y; av[6] = a1.z; av[7] = a1.w;
            ull bb[4];
            bb[0] = *(const ull*)&Bs[kk][2 * tx];
            bb[1] = *(const ull*)&Bs[kk][2 * tx + 32];
            bb[2] = *(const ull*)&Bs[kk][2 * tx + 64];
            bb[3] = *(const ull*)&Bs[kk][2 * tx + 96];
#pragma unroll
            for (int i = 0; i < 8; i++) {
                ull aa = pack2(av[i], av[i]);
                fma2(acc[i][0], aa, bb[0]);
                fma2(acc[i][1], aa, bb[1]);
                fma2(acc[i][2], aa, bb[2]);
                fma2(acc[i][3], aa, bb[3]);
            }
        }
        __syncthreads();
    }

#pragma unroll
    for (int i = 0; i < 8; i++) {
        const int m = m0 + ty * 8 + i;
#pragma unroll
        for (int u = 0; u < 4; u++) {
            const int n = n0 + 2 * (tx + 16 * u);
            if (n < N) {
                float2 f = unpack2(acc[i][u]);
                *(float2*)(C + (size_t)m * N + n) = f;
            }
        }
    }
}

// =====================================================================
// RoPE in-place on q (16 heads) and k (8 heads) sections of qkv
// =====================================================================
__global__ void rope_kernel(float* __restrict__ qkv,
                            const float* __restrict__ cs,
                            const float* __restrict__ sn)
{
    const int token = blockIdx.x;           // 0..4095
    const int s = token & (Sc - 1);
    float* row = qkv + (size_t)token * QKVOUTc;
    for (int p = threadIdx.x; p < 24 * 64; p += blockDim.x) {
        const int head = p >> 6;
        const int d = p & 63;
        float* base = (head < 16) ? (row + head * HDc)
                                  : (row + K_OFF + (head - 16) * HDc);
        const float x1 = base[d];
        const float x2 = base[d + 64];
        const float c1 = cs[s * HDc + d],      s1 = sn[s * HDc + d];
        const float c2 = cs[s * HDc + d + 64], s2 = sn[s * HDc + d + 64];
        base[d]      = x1 * c1 - x2 * s1;
        base[d + 64] = x2 * c2 + x1 * s2;
    }
}

// =====================================================================
// Flash attention + gate: per CTA: (b, h, 128 q-rows), loop 64-wide KV tiles
// =====================================================================
#define BQ 128
#define BKV 64
#define QS_STR 132   // Qs[d][r]
#define KS_STR 68    // Ks[d][c]
#define VS_STR 132   // Vs[j][d]
#define PS_STR 132   // Ps[c][r]   (transposed scores/probs)
#define ATT_SMEM_FLOATS (128*QS_STR + 128*KS_STR + 64*VS_STR + 64*PS_STR + 3*128)

__global__ __launch_bounds__(256, 1) void attn_kernel(
    const float* __restrict__ qkv, float* __restrict__ out)
{
    extern __shared__ float sm[];
    float* Qs   = sm;
    float* Ks   = Qs + 128 * QS_STR;
    float* Vs   = Ks + 128 * KS_STR;
    float* Ps   = Vs + 64 * VS_STR;
    float* m_s  = Ps + 64 * PS_STR;
    float* l_s  = m_s + 128;
    float* al_s = l_s + 128;

    const int tid = threadIdx.x;
    const int b = blockIdx.z;
    const int h = blockIdx.y;
    const int q0 = blockIdx.x * BQ;
    const int kvh = h >> 1;                 // rep = NH/NKV = 2
    const float scale = 0.08838834764831845f; // 1/sqrt(128)

    const float* Qbase = qkv + (size_t)(b * Sc + q0) * QKVOUTc + h * HDc;
    const float* Kbase = qkv + (size_t)(b * Sc) * QKVOUTc + K_OFF + kvh * HDc;
    const float* Vbase = qkv + (size_t)(b * Sc) * QKVOUTc + V_OFF + kvh * HDc;

    // ---- load Q tile transposed to [d][r] ----
#pragma unroll
    for (int t = 0; t < 16; t++) {
        const int idx = tid + t * 256;
        const int row = idx >> 5, d4 = idx & 31;
        float4 v = *(const float4*)(Qbase + (size_t)row * QKVOUTc + d4 * 4);
        Qs[(d4 * 4 + 0) * QS_STR + row] = v.x;
        Qs[(d4 * 4 + 1) * QS_STR + row] = v.y;
        Qs[(d4 * 4 + 2) * QS_STR + row] = v.z;
        Qs[(d4 * 4 + 3) * QS_STR + row] = v.w;
    }
    if (tid < 128) { m_s[tid] = -1e30f; l_s[tid] = 0.0f; }

    const int ry = tid >> 4;   // 0..15 -> rows ry*8..ry*8+7
    const int tx = tid & 15;   // col-pair groups

    ull acc[8][4];
#pragma unroll
    for (int i = 0; i < 8; i++)
#pragma unroll
        for (int u = 0; u < 4; u++) acc[i][u] = 0ull;

    for (int kt = 0; kt < Sc / BKV; kt++) {
        __syncthreads();   // protect Ks/Vs/Ps from previous iteration consumers
        const int k0 = kt * BKV;
#pragma unroll
        for (int t = 0; t < 8; t++) {
            const int idx = tid + t * 256;
            const int row = idx >> 5, d4 = idx & 31;
            float4 k4 = *(const float4*)(Kbase + (size_t)(k0 + row) * QKVOUTc + d4 * 4);
            Ks[(d4 * 4 + 0) * KS_STR + row] = k4.x;
            Ks[(d4 * 4 + 1) * KS_STR + row] = k4.y;
            Ks[(d4 * 4 + 2) * KS_STR + row] = k4.z;
            Ks[(d4 * 4 + 3) * KS_STR + row] = k4.w;
            float4 v4 = *(const float4*)(Vbase + (size_t)(k0 + row) * QKVOUTc + d4 * 4);
            *(float4*)(Vs + row * VS_STR + d4 * 4) = v4;
        }
        __syncthreads();

        // ---- phase 1: S = Q K^T (rows ry*8, col-pairs {tx, tx+16}) ----
        {
            ull sacc[8][2];
#pragma unroll
            for (int i = 0; i < 8; i++) { sacc[i][0] = 0ull; sacc[i][1] = 0ull; }
#pragma unroll 4
            for (int d = 0; d < HDc; d++) {
                float4 qa = *(const float4*)(Qs + d * QS_STR + ry * 8);
                float4 qb = *(const float4*)(Qs + d * QS_STR + ry * 8 + 4);
                float qv[8];
                qv[0] = qa.x; qv[1] = qa.y; qv[2] = qa.z; qv[3] = qa.w;
                qv[4] = qb.x; qv[5] = qb.y; qv[6] = qb.z; qv[7] = qb.w;
                ull kp0 = *(const ull*)(Ks + d * KS_STR + 2 * tx);
                ull kp1 = *(const ull*)(Ks + d * KS_STR + 2 * tx + 32);
#pragma unroll
                for (int i = 0; i < 8; i++) {
                    ull aa = pack2(qv[i], qv[i]);
                    fma2(sacc[i][0], aa, kp0);
                    fma2(sacc[i][1], aa, kp1);
                }
            }
            // write P transposed [c][r], scaled
#pragma unroll
            for (int u = 0; u < 2; u++) {
                float lo[8], hi[8];
#pragma unroll
                for (int i = 0; i < 8; i++) {
                    float2 f = unpack2(sacc[i][u]);
                    lo[i] = f.x * scale; hi[i] = f.y * scale;
                }
                const int c = 2 * (tx + 16 * u);
                float* p0 = Ps + c * PS_STR + ry * 8;
                *(float4*)(p0)     = make_float4(lo[0], lo[1], lo[2], lo[3]);
                *(float4*)(p0 + 4) = make_float4(lo[4], lo[5], lo[6], lo[7]);
                float* p1 = p0 + PS_STR;
                *(float4*)(p1)     = make_float4(hi[0], hi[1], hi[2], hi[3]);
                *(float4*)(p1 + 4) = make_float4(hi[4], hi[5], hi[6], hi[7]);
            }
        }
        __syncthreads();

        // ---- online softmax: 2 threads per row ----
        {
            const int r = tid >> 1;
            const int half = tid & 1;
            const int cbase = half * 32;
            const float mold = m_s[r];
            float mx = -1e30f;
#pragma unroll
            for (int c = 0; c < 32; c++)
                mx = fmaxf(mx, Ps[(cbase + c) * PS_STR + r]);
            mx = fmaxf(mx, __shfl_xor_sync(0xffffffffu, mx, 1));
            const float mnew = fmaxf(mold, mx);
            const float alpha = __expf(mold - mnew);
            float sum = 0.0f;
#pragma unroll
            for (int c = 0; c < 32; c++) {
                float p = __expf(Ps[(cbase + c) * PS_STR + r] - mnew);
                Ps[(cbase + c) * PS_STR + r] = p;
                sum += p;
            }
            sum += __shfl_xor_sync(0xffffffffu, sum, 1);
            if (half == 0) {
                m_s[r] = mnew;
                l_s[r] = l_s[r] * alpha + sum;
                al_s[r] = alpha;
            }
        }
        __syncthreads();

        // ---- phase 2: O = O*alpha + P V ----
        {
            ull apack[8];
#pragma unroll
            for (int i = 0; i < 8; i++) {
                float a = al_s[ry * 8 + i];
                apack[i] = pack2(a, a);
            }
#pragma unroll
            for (int i = 0; i < 8; i++)
#pragma unroll
                for (int u = 0; u < 4; u++) mul2(acc[i][u], apack[i]);

#pragma unroll 2
            for (int j = 0; j < BKV; j++) {
                float4 pa = *(const float4*)(Ps + j * PS_STR + ry * 8);
                float4 pb = *(const float4*)(Ps + j * PS_STR + ry * 8 + 4);
                float pv[8];
                pv[0] = pa.x; pv[1] = pa.y; pv[2] = pa.z; pv[3] = pa.w;
                pv[4] = pb.x; pv[5] = pb.y; pv[6] = pb.z; pv[7] = pb.w;
                ull vv[4];
                vv[0] = *(const ull*)(Vs + j * VS_STR + 2 * tx);
                vv[1] = *(const ull*)(Vs + j * VS_STR + 2 * tx + 32);
                vv[2] = *(const ull*)(Vs + j * VS_STR + 2 * tx + 64);
                vv[3] = *(const ull*)(Vs + j * VS_STR + 2 * tx + 96);
#pragma unroll
                for (int i = 0; i < 8; i++) {
                    ull pp = pack2(pv[i], pv[i]);
                    fma2(acc[i][0], pp, vv[0]);
                    fma2(acc[i][1], pp, vv[1]);
                    fma2(acc[i][2], pp, vv[2]);
                    fma2(acc[i][3], pp, vv[3]);
                }
            }
        }
    }

    // ---- epilogue: divide by l, apply sigmoid(gate), store ----
    const float* gate_ptr = qkv + (size_t)(b * Sc + q0) * QKVOUTc + HIDc + h;
    float* outbase = out + (size_t)(b * Sc + q0) * (NHc * HDc) + h * HDc;
#pragma unroll
    for (int i = 0; i < 8; i++) {
        const int r = ry * 8 + i;
        const float g = gate_ptr[(size_t)r * QKVOUTc];
        const float sig = 1.0f / (1.0f + __expf(-g));
        const float sc = sig / l_s[r];
#pragma unroll
        for (int u = 0; u < 4; u++) {
            float2 f = unpack2(acc[i][u]);
            f.x *= sc; f.y *= sc;
            *(float2*)(outbase + (size_t)r * (NHc * HDc) + 2 * (tx + 16 * u)) = f;
        }
    }
}

// =====================================================================
// launch
// =====================================================================
extern "C" void kernel_launch(void* const* d_in, const int* in_sizes, int n_in,
                              void* d_out, int out_size)
{
    const float* hs   = (const float*)d_in[0];   // hidden_states [B,S,HID]
    const float* cosb = (const float*)d_in[1];   // cos [S,HD]
    const float* sinb = (const float*)d_in[2];   // sin [S,HD]
    const float* wqkv = (const float*)d_in[3];   // [QKV_OUT, HID]
    const float* wo   = (const float*)d_in[4];   // [HID, NH*HD]
    float* out = (float*)d_out;

    float *qkv, *attn;
    cudaGetSymbolAddress((void**)&qkv, g_qkv);
    cudaGetSymbolAddress((void**)&attn, g_attn);

    // 1) qkv = hs @ w_qkv^T   (M=4096, N=4112, K=2048)
    sgemm_nt<<<dim3((QKVOUTc + 127) / 128, Mrows / 128), 256>>>(
        hs, wqkv, qkv, Mrows, QKVOUTc, HIDc);

    // 2) RoPE in place on q/k
    rope_kernel<<<Mrows, 256>>>(qkv, cosb, sinb);

    // 3) attention + gate -> attn [4096, 2048]
    const size_t shmem = (size_t)ATT_SMEM_FLOATS * sizeof(float);
    cudaFuncSetAttribute(attn_kernel, cudaFuncAttributeMaxDynamicSharedMemorySize,
                         (int)shmem);
    attn_kernel<<<dim3(Sc / BQ, NHc, Bc), 256, shmem>>>(qkv, attn);

    // 4) out = attn @ w_o^T   (M=4096, N=2048, K=2048)
    sgemm_nt<<<dim3(HIDc / 128, Mrows / 128), 256>>>(
        attn, wo, out, Mrows, HIDc, HIDc);
}

// round 7
// speedup vs baseline: 1.0007x; 1.0007x over previous
#include <cuda_runtime.h>
#include <cuda_bf16.h>
#include <cstdint>

typedef unsigned long long ull;

// ---------------- problem constants ----------------
#define Bc      2
#define Sc      2048
#define HIDc    2048
#define NHc     16
#define NKVc    8
#define HDc     128
#define GATEc   16
#define KVDIMc  (NKVc * HDc)          // 1024
#define QKVOUTc (HIDc + GATEc + 2 * KVDIMc)  // 4112
#define Mrows   (Bc * Sc)             // 4096
#define K_OFF   (HIDc + GATEc)        // 2064
#define V_OFF   (HIDc + GATEc + KVDIMc) // 3088

// ---------------- scratch (no allocations allowed) ----------------
__device__ float g_qkv[(size_t)Mrows * QKVOUTc];   // ~67 MB
__device__ float g_attn[(size_t)Mrows * HIDc];     // ~34 MB

// ---------------- f32x2 packed-FMA helpers ----------------
__device__ __forceinline__ ull pack2(float lo, float hi) {
    ull r;
    asm("mov.b64 %0, {%1, %2};" : "=l"(r) : "f"(lo), "f"(hi));
    return r;
}
__device__ __forceinline__ float2 unpack2(ull v) {
    float2 f;
    asm("mov.b64 {%0, %1}, %2;" : "=f"(f.x), "=f"(f.y) : "l"(v));
    return f;
}
__device__ __forceinline__ void fma2(ull& d, ull a, ull b) {
    asm("fma.rn.f32x2 %0, %1, %2, %0;" : "+l"(d) : "l"(a), "l"(b));
}
__device__ __forceinline__ void mul2(ull& d, ull a) {
    asm("mul.rn.f32x2 %0, %0, %1;" : "+l"(d) : "l"(a));
}

// =====================================================================
// Generic C[M,N] = A[M,K] @ B[N,K]^T  (both row-major, K contiguous)
// 128x128 tile, BK=16, 256 threads, 8 rows x 4 col-pairs per thread (f32x2)
// =====================================================================
__global__ __launch_bounds__(256, 2) void sgemm_nt(
    const float* __restrict__ A, const float* __restrict__ B,
    float* __restrict__ C, int M, int N, int K)
{
    __shared__ float As[16][132];
    __shared__ float Bs[16][132];

    const int tid = threadIdx.x;
    const int m0 = blockIdx.y * 128;
    const int n0 = blockIdx.x * 128;
    const int tx = tid & 15;        // col group
    const int ty = tid >> 4;        // row group

    ull acc[8][4];
#pragma unroll
    for (int i = 0; i < 8; i++)
#pragma unroll
        for (int u = 0; u < 4; u++) acc[i][u] = 0ull;

    const int lr = tid >> 2;        // 0..63 (tile row within load pass)
    const int lk = tid & 3;         // 0..3  (float4 index within 16 k's)

    for (int k0 = 0; k0 < K; k0 += 16) {
#pragma unroll
        for (int t = 0; t < 2; t++) {
            const int row = lr + t * 64;
            float4 a4 = *(const float4*)(A + (size_t)(m0 + row) * K + k0 + lk * 4);
            As[lk * 4 + 0][row] = a4.x;
            As[lk * 4 + 1][row] = a4.y;
            As[lk * 4 + 2][row] = a4.z;
            As[lk * 4 + 3][row] = a4.w;
            const int n = n0 + row;
            float4 b4 = make_float4(0.f, 0.f, 0.f, 0.f);
            if (n < N) b4 = *(const float4*)(B + (size_t)n * K + k0 + lk * 4);
            Bs[lk * 4 + 0][row] = b4.x;
            Bs[lk * 4 + 1][row] = b4.y;
            Bs[lk * 4 + 2][row] = b4.z;
            Bs[lk * 4 + 3][row] = b4.w;
        }
        __syncthreads();

#pragma unroll
        for (int kk = 0; kk < 16; kk++) {
            float4 a0 = *(const float4*)&As[kk][ty * 8];
            float4 a1 = *(const float4*)&As[kk][ty * 8 + 4];
            float av[8];
            av[0] = a0.x; av[1] = a0.y; av[2] = a0.z; av[3] = a0.w;
            av[4] = a1.x; av[5] = a1.y; av[6] = a1.z; av[7] = a1.w;
            ull bb[4];
            bb[0] = *(const ull*)&Bs[kk][2 * tx];
            bb[1] = *(const ull*)&Bs[kk][2 * tx + 32];
            bb[2] = *(const ull*)&Bs[kk][2 * tx + 64];
            bb[3] = *(const ull*)&Bs[kk][2 * tx + 96];
#pragma unroll
            for (int i = 0; i < 8; i++) {
                ull aa = pack2(av[i], av[i]);
                fma2(acc[i][0], aa, bb[0]);
                fma2(acc[i][1], aa, bb[1]);
                fma2(acc[i][2], aa, bb[2]);
                fma2(acc[i][3], aa, bb[3]);
            }
        }
        __syncthreads();
    }

#pragma unroll
    for (int i = 0; i < 8; i++) {
        const int m = m0 + ty * 8 + i;
#pragma unroll
        for (int u = 0; u < 4; u++) {
            const int n = n0 + 2 * (tx + 16 * u);
            if (n < N) {
                float2 f = unpack2(acc[i][u]);
                *(float2*)(C + (size_t)m * N + n) = f;
            }
        }
    }
}

// =====================================================================
// RoPE in-place on q (16 heads) and k (8 heads) sections of qkv
// =====================================================================
__global__ void rope_kernel(float* __restrict__ qkv,
                            const float* __restrict__ cs,
                            const float* __restrict__ sn)
{
    const int token = blockIdx.x;           // 0..4095
    const int s = token & (Sc - 1);
    float* row = qkv + (size_t)token * QKVOUTc;
    for (int p = threadIdx.x; p < 24 * 64; p += blockDim.x) {
        const int head = p >> 6;
        const int d = p & 63;
        float* base = (head < 16) ? (row + head * HDc)
                                  : (row + K_OFF + (head - 16) * HDc);
        const float x1 = base[d];
        const float x2 = base[d + 64];
        const float c1 = cs[s * HDc + d],      s1 = sn[s * HDc + d];
        const float c2 = cs[s * HDc + d + 64], s2 = sn[s * HDc + d + 64];
        base[d]      = x1 * c1 - x2 * s1;
        base[d + 64] = x2 * c2 + x1 * s2;
    }
}

// =====================================================================
// Flash attention + gate: per CTA: (b, h, 128 q-rows), loop 64-wide KV tiles
// =====================================================================
#define BQ 128
#define BKV 64
#define QS_STR 132   // Qs[d][r]
#define KS_STR 68    // Ks[d][c]
#define VS_STR 132   // Vs[j][d]
#define PS_STR 132   // Ps[c][r]   (transposed scores/probs)
#define ATT_SMEM_FLOATS (128*QS_STR + 128*KS_STR + 64*VS_STR + 64*PS_STR + 3*128)

__global__ __launch_bounds__(256, 1) void attn_kernel(
    const float* __restrict__ qkv, float* __restrict__ out)
{
    extern __shared__ float sm[];
    float* Qs   = sm;
    float* Ks   = Qs + 128 * QS_STR;
    float* Vs   = Ks + 128 * KS_STR;
    float* Ps   = Vs + 64 * VS_STR;
    float* m_s  = Ps + 64 * PS_STR;
    float* l_s  = m_s + 128;
    float* al_s = l_s + 128;

    const int tid = threadIdx.x;
    const int b = blockIdx.z;
    const int h = blockIdx.y;
    const int q0 = blockIdx.x * BQ;
    const int kvh = h >> 1;                 // rep = NH/NKV = 2
    const float scale = 0.08838834764831845f; // 1/sqrt(128)

    const float* Qbase = qkv + (size_t)(b * Sc + q0) * QKVOUTc + h * HDc;
    const float* Kbase = qkv + (size_t)(b * Sc) * QKVOUTc + K_OFF + kvh * HDc;
    const float* Vbase = qkv + (size_t)(b * Sc) * QKVOUTc + V_OFF + kvh * HDc;

    // ---- load Q tile transposed to [d][r] ----
#pragma unroll
    for (int t = 0; t < 16; t++) {
        const int idx = tid + t * 256;
        const int row = idx >> 5, d4 = idx & 31;
        float4 v = *(const float4*)(Qbase + (size_t)row * QKVOUTc + d4 * 4);
        Qs[(d4 * 4 + 0) * QS_STR + row] = v.x;
        Qs[(d4 * 4 + 1) * QS_STR + row] = v.y;
        Qs[(d4 * 4 + 2) * QS_STR + row] = v.z;
        Qs[(d4 * 4 + 3) * QS_STR + row] = v.w;
    }
    if (tid < 128) { m_s[tid] = -1e30f; l_s[tid] = 0.0f; }

    const int ry = tid >> 4;   // 0..15 -> rows ry*8..ry*8+7
    const int tx = tid & 15;   // col-pair groups

    ull acc[8][4];
#pragma unroll
    for (int i = 0; i < 8; i++)
#pragma unroll
        for (int u = 0; u < 4; u++) acc[i][u] = 0ull;

    for (int kt = 0; kt < Sc / BKV; kt++) {
        __syncthreads();   // protect Ks/Vs/Ps from previous iteration consumers
        const int k0 = kt * BKV;
#pragma unroll
        for (int t = 0; t < 8; t++) {
            const int idx = tid + t * 256;
            const int row = idx >> 5, d4 = idx & 31;
            float4 k4 = *(const float4*)(Kbase + (size_t)(k0 + row) * QKVOUTc + d4 * 4);
            Ks[(d4 * 4 + 0) * KS_STR + row] = k4.x;
            Ks[(d4 * 4 + 1) * KS_STR + row] = k4.y;
            Ks[(d4 * 4 + 2) * KS_STR + row] = k4.z;
            Ks[(d4 * 4 + 3) * KS_STR + row] = k4.w;
            float4 v4 = *(const float4*)(Vbase + (size_t)(k0 + row) * QKVOUTc + d4 * 4);
            *(float4*)(Vs + row * VS_STR + d4 * 4) = v4;
        }
        __syncthreads();

        // ---- phase 1: S = Q K^T (rows ry*8, col-pairs {tx, tx+16}) ----
        {
            ull sacc[8][2];
#pragma unroll
            for (int i = 0; i < 8; i++) { sacc[i][0] = 0ull; sacc[i][1] = 0ull; }
#pragma unroll 4
            for (int d = 0; d < HDc; d++) {
                float4 qa = *(const float4*)(Qs + d * QS_STR + ry * 8);
                float4 qb = *(const float4*)(Qs + d * QS_STR + ry * 8 + 4);
                float qv[8];
                qv[0] = qa.x; qv[1] = qa.y; qv[2] = qa.z; qv[3] = qa.w;
                qv[4] = qb.x; qv[5] = qb.y; qv[6] = qb.z; qv[7] = qb.w;
                ull kp0 = *(const ull*)(Ks + d * KS_STR + 2 * tx);
                ull kp1 = *(const ull*)(Ks + d * KS_STR + 2 * tx + 32);
#pragma unroll
                for (int i = 0; i < 8; i++) {
                    ull aa = pack2(qv[i], qv[i]);
                    fma2(sacc[i][0], aa, kp0);
                    fma2(sacc[i][1], aa, kp1);
                }
            }
            // write P transposed [c][r], scaled
#pragma unroll
            for (int u = 0; u < 2; u++) {
                float lo[8], hi[8];
#pragma unroll
                for (int i = 0; i < 8; i++) {
                    float2 f = unpack2(sacc[i][u]);
                    lo[i] = f.x * scale; hi[i] = f.y * scale;
                }
                const int c = 2 * (tx + 16 * u);
                float* p0 = Ps + c * PS_STR + ry * 8;
                *(float4*)(p0)     = make_float4(lo[0], lo[1], lo[2], lo[3]);
                *(float4*)(p0 + 4) = make_float4(lo[4], lo[5], lo[6], lo[7]);
                float* p1 = p0 + PS_STR;
                *(float4*)(p1)     = make_float4(hi[0], hi[1], hi[2], hi[3]);
                *(float4*)(p1 + 4) = make_float4(hi[4], hi[5], hi[6], hi[7]);
            }
        }
        __syncthreads();

        // ---- online softmax: 2 threads per row ----
        {
            const int r = tid >> 1;
            const int half = tid & 1;
            const int cbase = half * 32;
            const float mold = m_s[r];
            float mx = -1e30f;
#pragma unroll
            for (int c = 0; c < 32; c++)
                mx = fmaxf(mx, Ps[(cbase + c) * PS_STR + r]);
            mx = fmaxf(mx, __shfl_xor_sync(0xffffffffu, mx, 1));
            const float mnew = fmaxf(mold, mx);
            const float alpha = __expf(mold - mnew);
            float sum = 0.0f;
#pragma unroll
            for (int c = 0; c < 32; c++) {
                float p = __expf(Ps[(cbase + c) * PS_STR + r] - mnew);
                Ps[(cbase + c) * PS_STR + r] = p;
                sum += p;
            }
            sum += __shfl_xor_sync(0xffffffffu, sum, 1);
            if (half == 0) {
                m_s[r] = mnew;
                l_s[r] = l_s[r] * alpha + sum;
                al_s[r] = alpha;
            }
        }
        __syncthreads();

        // ---- phase 2: O = O*alpha + P V ----
        {
            ull apack[8];
#pragma unroll
            for (int i = 0; i < 8; i++) {
                float a = al_s[ry * 8 + i];
                apack[i] = pack2(a, a);
            }
#pragma unroll
            for (int i = 0; i < 8; i++)
#pragma unroll
                for (int u = 0; u < 4; u++) mul2(acc[i][u], apack[i]);

#pragma unroll 2
            for (int j = 0; j < BKV; j++) {
                float4 pa = *(const float4*)(Ps + j * PS_STR + ry * 8);
                float4 pb = *(const float4*)(Ps + j * PS_STR + ry * 8 + 4);
                float pv[8];
                pv[0] = pa.x; pv[1] = pa.y; pv[2] = pa.z; pv[3] = pa.w;
                pv[4] = pb.x; pv[5] = pb.y; pv[6] = pb.z; pv[7] = pb.w;
                ull vv[4];
                vv[0] = *(const ull*)(Vs + j * VS_STR + 2 * tx);
                vv[1] = *(const ull*)(Vs + j * VS_STR + 2 * tx + 32);
                vv[2] = *(const ull*)(Vs + j * VS_STR + 2 * tx + 64);
                vv[3] = *(const ull*)(Vs + j * VS_STR + 2 * tx + 96);
#pragma unroll
                for (int i = 0; i < 8; i++) {
                    ull pp = pack2(pv[i], pv[i]);
                    fma2(acc[i][0], pp, vv[0]);
                    fma2(acc[i][1], pp, vv[1]);
                    fma2(acc[i][2], pp, vv[2]);
                    fma2(acc[i][3], pp, vv[3]);
                }
            }
        }
    }

    // ---- epilogue: divide by l, apply sigmoid(gate), store ----
    const float* gate_ptr = qkv + (size_t)(b * Sc + q0) * QKVOUTc + HIDc + h;
    float* outbase = out + (size_t)(b * Sc + q0) * (NHc * HDc) + h * HDc;
#pragma unroll
    for (int i = 0; i < 8; i++) {
        const int r = ry * 8 + i;
        const float g = gate_ptr[(size_t)r * QKVOUTc];
        const float sig = 1.0f / (1.0f + __expf(-g));
        const float sc = sig / l_s[r];
#pragma unroll
        for (int u = 0; u < 4; u++) {
            float2 f = unpack2(acc[i][u]);
            f.x *= sc; f.y *= sc;
            *(float2*)(outbase + (size_t)r * (NHc * HDc) + 2 * (tx + 16 * u)) = f;
        }
    }
}

// =====================================================================
// launch
// =====================================================================
extern "C" void kernel_launch(void* const* d_in, const int* in_sizes, int n_in,
                              void* d_out, int out_size)
{
    const float* hs   = (const float*)d_in[0];   // hidden_states [B,S,HID]
    const float* cosb = (const float*)d_in[1];   // cos [S,HD]
    const float* sinb = (const float*)d_in[2];   // sin [S,HD]
    const float* wqkv = (const float*)d_in[3];   // [QKV_OUT, HID]
    const float* wo   = (const float*)d_in[4];   // [HID, NH*HD]
    float* out = (float*)d_out;

    float *qkv, *attn;
    cudaGetSymbolAddress((void**)&qkv, g_qkv);
    cudaGetSymbolAddress((void**)&attn, g_attn);

    // 1) qkv = hs @ w_qkv^T   (M=4096, N=4112, K=2048)
    sgemm_nt<<<dim3((QKVOUTc + 127) / 128, Mrows / 128), 256>>>(
        hs, wqkv, qkv, Mrows, QKVOUTc, HIDc);

    // 2) RoPE in place on q/k
    rope_kernel<<<Mrows, 256>>>(qkv, cosb, sinb);

    // 3) attention + gate -> attn [4096, 2048]
    const size_t shmem = (size_t)ATT_SMEM_FLOATS * sizeof(float);
    cudaFuncSetAttribute(attn_kernel, cudaFuncAttributeMaxDynamicSharedMemorySize,
                         (int)shmem);
    attn_kernel<<<dim3(Sc / BQ, NHc, Bc), 256, shmem>>>(qkv, attn);

    // 4) out = attn @ w_o^T   (M=4096, N=2048, K=2048)
    sgemm_nt<<<dim3(HIDc / 128, Mrows / 128), 256>>>(
        attn, wo, out, Mrows, HIDc, HIDc);
}

// round 12
// speedup vs baseline: 1.0008x; 1.0001x over previous
#include <cuda_runtime.h>
#include <cuda_bf16.h>
#include <cstdint>

typedef unsigned long long ull;

// ---------------- problem constants ----------------
#define Bc      2
#define Sc      2048
#define HIDc    2048
#define NHc     16
#define NKVc    8
#define HDc     128
#define GATEc   16
#define KVDIMc  (NKVc * HDc)          // 1024
#define QKVOUTc (HIDc + GATEc + 2 * KVDIMc)  // 4112
#define Mrows   (Bc * Sc)             // 4096
#define K_OFF   (HIDc + GATEc)        // 2064
#define V_OFF   (HIDc + GATEc + KVDIMc) // 3088

// ---------------- scratch (no allocations allowed) ----------------
__device__ float g_qkv[(size_t)Mrows * QKVOUTc];   // ~67 MB
__device__ float g_attn[(size_t)Mrows * HIDc];     // ~34 MB

// ---------------- f32x2 packed-FMA helpers ----------------
__device__ __forceinline__ ull pack2(float lo, float hi) {
    ull r;
    asm("mov.b64 %0, {%1, %2};" : "=l"(r) : "f"(lo), "f"(hi));
    return r;
}
__device__ __forceinline__ float2 unpack2(ull v) {
    float2 f;
    asm("mov.b64 {%0, %1}, %2;" : "=f"(f.x), "=f"(f.y) : "l"(v));
    return f;
}
__device__ __forceinline__ void fma2(ull& d, ull a, ull b) {
    asm("fma.rn.f32x2 %0, %1, %2, %0;" : "+l"(d) : "l"(a), "l"(b));
}
__device__ __forceinline__ void mul2(ull& d, ull a) {
    asm("mul.rn.f32x2 %0, %0, %1;" : "+l"(d) : "l"(a));
}

// =====================================================================
// Generic C[M,N] = A[M,K] @ B[N,K]^T  (both row-major, K contiguous)
// 128x128 tile, BK=16, 256 threads, 8 rows x 4 col-pairs per thread (f32x2)
// =====================================================================
__global__ __launch_bounds__(256, 2) void sgemm_nt(
    const float* __restrict__ A, const float* __restrict__ B,
    float* __restrict__ C, int M, int N, int K)
{
    __shared__ float As[16][132];
    __shared__ float Bs[16][132];

    const int tid = threadIdx.x;
    const int m0 = blockIdx.y * 128;
    const int n0 = blockIdx.x * 128;
    const int tx = tid & 15;        // col group
    const int ty = tid >> 4;        // row group

    ull acc[8][4];
#pragma unroll
    for (int i = 0; i < 8; i++)
#pragma unroll
        for (int u = 0; u < 4; u++) acc[i][u] = 0ull;

    const int lr = tid >> 2;        // 0..63 (tile row within load pass)
    const int lk = tid & 3;         // 0..3  (float4 index within 16 k's)

    for (int k0 = 0; k0 < K; k0 += 16) {
#pragma unroll
        for (int t = 0; t < 2; t++) {
            const int row = lr + t * 64;
            float4 a4 = *(const float4*)(A + (size_t)(m0 + row) * K + k0 + lk * 4);
            As[lk * 4 + 0][row] = a4.x;
            As[lk * 4 + 1][row] = a4.y;
            As[lk * 4 + 2][row] = a4.z;
            As[lk * 4 + 3][row] = a4.w;
            const int n = n0 + row;
            float4 b4 = make_float4(0.f, 0.f, 0.f, 0.f);
            if (n < N) b4 = *(const float4*)(B + (size_t)n * K + k0 + lk * 4);
            Bs[lk * 4 + 0][row] = b4.x;
            Bs[lk * 4 + 1][row] = b4.y;
            Bs[lk * 4 + 2][row] = b4.z;
            Bs[lk * 4 + 3][row] = b4.w;
        }
        __syncthreads();

#pragma unroll
        for (int kk = 0; kk < 16; kk++) {
            float4 a0 = *(const float4*)&As[kk][ty * 8];
            float4 a1 = *(const float4*)&As[kk][ty * 8 + 4];
            float av[8];
            av[0] = a0.x; av[1] = a0.y; av[2] = a0.z; av[3] = a0.w;
            av[4] = a1.x; av[5] = a1.y; av[6] = a1.z; av[7] = a1.w;
            ull bb[4];
            bb[0] = *(const ull*)&Bs[kk][2 * tx];
            bb[1] = *(const ull*)&Bs[kk][2 * tx + 32];
            bb[2] = *(const ull*)&Bs[kk][2 * tx + 64];
            bb[3] = *(const ull*)&Bs[kk][2 * tx + 96];
#pragma unroll
            for (int i = 0; i < 8; i++) {
                ull aa = pack2(av[i], av[i]);
                fma2(acc[i][0], aa, bb[0]);
                fma2(acc[i][1], aa, bb[1]);
                fma2(acc[i][2], aa, bb[2]);
                fma2(acc[i][3], aa, bb[3]);
            }
        }
        __syncthreads();
    }

#pragma unroll
    for (int i = 0; i < 8; i++) {
        const int m = m0 + ty * 8 + i;
#pragma unroll
        for (int u = 0; u < 4; u++) {
            const int n = n0 + 2 * (tx + 16 * u);
            if (n < N) {
                float2 f = unpack2(acc[i][u]);
                *(float2*)(C + (size_t)m * N + n) = f;
            }
        }
    }
}

// =====================================================================
// RoPE in-place on q (16 heads) and k (8 heads) sections of qkv
// =====================================================================
__global__ void rope_kernel(float* __restrict__ qkv,
                            const float* __restrict__ cs,
                            const float* __restrict__ sn)
{
    const int token = blockIdx.x;           // 0..4095
    const int s = token & (Sc - 1);
    float* row = qkv + (size_t)token * QKVOUTc;
    for (int p = threadIdx.x; p < 24 * 64; p += blockDim.x) {
        const int head = p >> 6;
        const int d = p & 63;
        float* base = (head < 16) ? (row + head * HDc)
                                  : (row + K_OFF + (head - 16) * HDc);
        const float x1 = base[d];
        const float x2 = base[d + 64];
        const float c1 = cs[s * HDc + d],      s1 = sn[s * HDc + d];
        const float c2 = cs[s * HDc + d + 64], s2 = sn[s * HDc + d + 64];
        base[d]      = x1 * c1 - x2 * s1;
        base[d + 64] = x2 * c2 + x1 * s2;
    }
}

// =====================================================================
// Flash attention + gate: per CTA: (b, h, 128 q-rows), loop 64-wide KV tiles
// =====================================================================
#define BQ 128
#define BKV 64
#define QS_STR 132   // Qs[d][r]
#define KS_STR 68    // Ks[d][c]
#define VS_STR 132   // Vs[j][d]
#define PS_STR 132   // Ps[c][r]   (transposed scores/probs)
#define ATT_SMEM_FLOATS (128*QS_STR + 128*KS_STR + 64*VS_STR + 64*PS_STR + 3*128)

__global__ __launch_bounds__(256, 1) void attn_kernel(
    const float* __restrict__ qkv, float* __restrict__ out)
{
    extern __shared__ float sm[];
    float* Qs   = sm;
    float* Ks   = Qs + 128 * QS_STR;
    float* Vs   = Ks + 128 * KS_STR;
    float* Ps   = Vs + 64 * VS_STR;
    float* m_s  = Ps + 64 * PS_STR;
    float* l_s  = m_s + 128;
    float* al_s = l_s + 128;

    const int tid = threadIdx.x;
    const int b = blockIdx.z;
    const int h = blockIdx.y;
    const int q0 = blockIdx.x * BQ;
    const int kvh = h >> 1;                 // rep = NH/NKV = 2
    const float scale = 0.08838834764831845f; // 1/sqrt(128)

    const float* Qbase = qkv + (size_t)(b * Sc + q0) * QKVOUTc + h * HDc;
    const float* Kbase = qkv + (size_t)(b * Sc) * QKVOUTc + K_OFF + kvh * HDc;
    const float* Vbase = qkv + (size_t)(b * Sc) * QKVOUTc + V_OFF + kvh * HDc;

    // ---- load Q tile transposed to [d][r] ----
#pragma unroll
    for (int t = 0; t < 16; t++) {
        const int idx = tid + t * 256;
        const int row = idx >> 5, d4 = idx & 31;
        float4 v = *(const float4*)(Qbase + (size_t)row * QKVOUTc + d4 * 4);
        Qs[(d4 * 4 + 0) * QS_STR + row] = v.x;
        Qs[(d4 * 4 + 1) * QS_STR + row] = v.y;
        Qs[(d4 * 4 + 2) * QS_STR + row] = v.z;
        Qs[(d4 * 4 + 3) * QS_STR + row] = v.w;
    }
    if (tid < 128) { m_s[tid] = -1e30f; l_s[tid] = 0.0f; }

    const int ry = tid >> 4;   // 0..15 -> rows ry*8..ry*8+7
    const int tx = tid & 15;   // col-pair groups

    ull acc[8][4];
#pragma unroll
    for (int i = 0; i < 8; i++)
#pragma unroll
        for (int u = 0; u < 4; u++) acc[i][u] = 0ull;

    for (int kt = 0; kt < Sc / BKV; kt++) {
        __syncthreads();   // protect Ks/Vs/Ps from previous iteration consumers
        const int k0 = kt * BKV;
#pragma unroll
        for (int t = 0; t < 8; t++) {
            const int idx = tid + t * 256;
            const int row = idx >> 5, d4 = idx & 31;
            float4 k4 = *(const float4*)(Kbase + (size_t)(k0 + row) * QKVOUTc + d4 * 4);
            Ks[(d4 * 4 + 0) * KS_STR + row] = k4.x;
            Ks[(d4 * 4 + 1) * KS_STR + row] = k4.y;
            Ks[(d4 * 4 + 2) * KS_STR + row] = k4.z;
            Ks[(d4 * 4 + 3) * KS_STR + row] = k4.w;
            float4 v4 = *(const float4*)(Vbase + (size_t)(k0 + row) * QKVOUTc + d4 * 4);
            *(float4*)(Vs + row * VS_STR + d4 * 4) = v4;
        }
        __syncthreads();

        // ---- phase 1: S = Q K^T (rows ry*8, col-pairs {tx, tx+16}) ----
        {
            ull sacc[8][2];
#pragma unroll
            for (int i = 0; i < 8; i++) { sacc[i][0] = 0ull; sacc[i][1] = 0ull; }
#pragma unroll 4
            for (int d = 0; d < HDc; d++) {
                float4 qa = *(const float4*)(Qs + d * QS_STR + ry * 8);
                float4 qb = *(const float4*)(Qs + d * QS_STR + ry * 8 + 4);
                float qv[8];
                qv[0] = qa.x; qv[1] = qa.y; qv[2] = qa.z; qv[3] = qa.w;
                qv[4] = qb.x; qv[5] = qb.y; qv[6] = qb.z; qv[7] = qb.w;
                ull kp0 = *(const ull*)(Ks + d * KS_STR + 2 * tx);
                ull kp1 = *(const ull*)(Ks + d * KS_STR + 2 * tx + 32);
#pragma unroll
                for (int i = 0; i < 8; i++) {
                    ull aa = pack2(qv[i], qv[i]);
                    fma2(sacc[i][0], aa, kp0);
                    fma2(sacc[i][1], aa, kp1);
                }
            }
            // write P transposed [c][r], scaled
#pragma unroll
            for (int u = 0; u < 2; u++) {
                float lo[8], hi[8];
#pragma unroll
                for (int i = 0; i < 8; i++) {
                    float2 f = unpack2(sacc[i][u]);
                    lo[i] = f.x * scale; hi[i] = f.y * scale;
                }
                const int c = 2 * (tx + 16 * u);
                float* p0 = Ps + c * PS_STR + ry * 8;
                *(float4*)(p0)     = make_float4(lo[0], lo[1], lo[2], lo[3]);
                *(float4*)(p0 + 4) = make_float4(lo[4], lo[5], lo[6], lo[7]);
                float* p1 = p0 + PS_STR;
                *(float4*)(p1)     = make_float4(hi[0], hi[1], hi[2], hi[3]);
                *(float4*)(p1 + 4) = make_float4(hi[4], hi[5], hi[6], hi[7]);
            }
        }
        __syncthreads();

        // ---- online softmax: 2 threads per row ----
        {
            const int r = tid >> 1;
            const int half = tid & 1;
            const int cbase = half * 32;
            const float mold = m_s[r];
            float mx = -1e30f;
#pragma unroll
            for (int c = 0; c < 32; c++)
                mx = fmaxf(mx, Ps[(cbase + c) * PS_STR + r]);
            mx = fmaxf(mx, __shfl_xor_sync(0xffffffffu, mx, 1));
            const float mnew = fmaxf(mold, mx);
            const float alpha = __expf(mold - mnew);
            float sum = 0.0f;
#pragma unroll
            for (int c = 0; c < 32; c++) {
                float p = __expf(Ps[(cbase + c) * PS_STR + r] - mnew);
                Ps[(cbase + c) * PS_STR + r] = p;
                sum += p;
            }
            sum += __shfl_xor_sync(0xffffffffu, sum, 1);
            if (half == 0) {
                m_s[r] = mnew;
                l_s[r] = l_s[r] * alpha + sum;
                al_s[r] = alpha;
            }
        }
        __syncthreads();

        // ---- phase 2: O = O*alpha + P V ----
        {
            ull apack[8];
#pragma unroll
            for (int i = 0; i < 8; i++) {
                float a = al_s[ry * 8 + i];
                apack[i] = pack2(a, a);
            }
#pragma unroll
            for (int i = 0; i < 8; i++)
#pragma unroll
                for (int u = 0; u < 4; u++) mul2(acc[i][u], apack[i]);

#pragma unroll 2
            for (int j = 0; j < BKV; j++) {
                float4 pa = *(const float4*)(Ps + j * PS_STR + ry * 8);
                float4 pb = *(const float4*)(Ps + j * PS_STR + ry * 8 + 4);
                float pv[8];
                pv[0] = pa.x; pv[1] = pa.y; pv[2] = pa.z; pv[3] = pa.w;
                pv[4] = pb.x; pv[5] = pb.y; pv[6] = pb.z; pv[7] = pb.w;
                ull vv[4];
                vv[0] = *(const ull*)(Vs + j * VS_STR + 2 * tx);
                vv[1] = *(const ull*)(Vs + j * VS_STR + 2 * tx + 32);
                vv[2] = *(const ull*)(Vs + j * VS_STR + 2 * tx + 64);
                vv[3] = *(const ull*)(Vs + j * VS_STR + 2 * tx + 96);
#pragma unroll
                for (int i = 0; i < 8; i++) {
                    ull pp = pack2(pv[i], pv[i]);
                    fma2(acc[i][0], pp, vv[0]);
                    fma2(acc[i][1], pp, vv[1]);
                    fma2(acc[i][2], pp, vv[2]);
                    fma2(acc[i][3], pp, vv[3]);
                }
            }
        }
    }

    // ---- epilogue: divide by l, apply sigmoid(gate), store ----
    const float* gate_ptr = qkv + (size_t)(b * Sc + q0) * QKVOUTc + HIDc + h;
    float* outbase = out + (size_t)(b * Sc + q0) * (NHc * HDc) + h * HDc;
#pragma unroll
    for (int i = 0; i < 8; i++) {
        const int r = ry * 8 + i;
        const float g = gate_ptr[(size_t)r * QKVOUTc];
        const float sig = 1.0f / (1.0f + __expf(-g));
        const float sc = sig / l_s[r];
#pragma unroll
        for (int u = 0; u < 4; u++) {
            float2 f = unpack2(acc[i][u]);
            f.x *= sc; f.y *= sc;
            *(float2*)(outbase + (size_t)r * (NHc * HDc) + 2 * (tx + 16 * u)) = f;
        }
    }
}

// =====================================================================
// launch
// =====================================================================
extern "C" void kernel_launch(void* const* d_in, const int* in_sizes, int n_in,
                              void* d_out, int out_size)
{
    const float* hs   = (const float*)d_in[0];   // hidden_states [B,S,HID]
    const float* cosb = (const float*)d_in[1];   // cos [S,HD]
    const float* sinb = (const float*)d_in[2];   // sin [S,HD]
    const float* wqkv = (const float*)d_in[3];   // [QKV_OUT, HID]
    const float* wo   = (const float*)d_in[4];   // [HID, NH*HD]
    float* out = (float*)d_out;

    float *qkv, *attn;
    cudaGetSymbolAddress((void**)&qkv, g_qkv);
    cudaGetSymbolAddress((void**)&attn, g_attn);

    // 1) qkv = hs @ w_qkv^T   (M=4096, N=4112, K=2048)
    sgemm_nt<<<dim3((QKVOUTc + 127) / 128, Mrows / 128), 256>>>(
        hs, wqkv, qkv, Mrows, QKVOUTc, HIDc);

    // 2) RoPE in place on q/k
    rope_kernel<<<Mrows, 256>>>(qkv, cosb, sinb);

    // 3) attention + gate -> attn [4096, 2048]
    const size_t shmem = (size_t)ATT_SMEM_FLOATS * sizeof(float);
    cudaFuncSetAttribute(attn_kernel, cudaFuncAttributeMaxDynamicSharedMemorySize,
                         (int)shmem);
    attn_kernel<<<dim3(Sc / BQ, NHc, Bc), 256, shmem>>>(qkv, attn);

    // 4) out = attn @ w_o^T   (M=4096, N=2048, K=2048)
    sgemm_nt<<<dim3(HIDc / 128, Mrows / 128), 256>>>(
        attn, wo, out, Mrows, HIDc, HIDc);
}